// round 10
// baseline (speedup 1.0000x reference)
#include <cuda_runtime.h>
#include <cuda_bf16.h>

#define FMAX 20908

// Repacked per-face record: 4 x float4 = 64B, 128B-aligned so each record
// lies in one 128B line.
// chunk0=(t00,t01,t02,t10) chunk1=(t11,t12,t20,t21) chunk2=(t22,n0,n1,n2) chunk3=pad
__device__ __align__(128) float4 g_face_pack[FMAX * 4];

__global__ __launch_bounds__(256) void repack_kernel(
    const float* __restrict__ triangles,    // [F,3,3]
    const float* __restrict__ face_normals, // [F,3]
    int F)
{
    int i = blockIdx.x * blockDim.x + threadIdx.x;
    if (i >= F * 3) return;
    int f = i / 3;
    int c = i - 3 * f;
    const float* t = triangles + (size_t)f * 9;
    float4 v;
    if (c == 0)      v = make_float4(t[0], t[1], t[2], t[3]);
    else if (c == 1) v = make_float4(t[4], t[5], t[6], t[7]);
    else {
        const float* n = face_normals + (size_t)f * 3;
        v = make_float4(t[8], n[0], n[1], n[2]);
    }
    g_face_pack[4*f + c] = v;
}

// 256 threads = 8 warps, 1 point/thread (R5 shape), but ALL strided global
// access is converted to dense 128B global transactions + conflict-free
// strided shared-memory transposes.
__global__ __launch_bounds__(256) void sd_smem_kernel(
    const float* __restrict__ points,        // [Q,3]
    const int*   __restrict__ closest_faces, // [Q]
    const float* __restrict__ closest_bcs,   // [Q,3]
    float* __restrict__ out,
    int Q)
{
    __shared__ float4 s_face[8 * 32 * 3];    // 12 KB, 48B record stride (conflict-free)
    __shared__ float  s_inp[8][96];          // 3 KB  points transpose
    __shared__ float  s_inb[8][96];          // 3 KB  bcs transpose
    __shared__ float  s_out[8][3][96];       // 9 KB  rn/cp/bc store transpose

    int tid  = threadIdx.x;
    int lane = tid & 31;
    int wrp  = tid >> 5;
    int q    = blockIdx.x * blockDim.x + tid;
    int wb   = q - lane;                     // warp's first point
    if (wb >= Q) return;
    bool full = (wb + 32 <= Q);

    float* rn_out = out + (size_t)Q;
    float* cp_out = out + (size_t)4 * Q;
    float* cf_out = out + (size_t)7 * Q;
    float* bc_out = out + (size_t)8 * Q;

    if (full) {
        int f = closest_faces[q];

        // dense cooperative input loads: 384B per array per warp, 24 lanes x 16B
        if (lane < 24) {
            int i4 = ((3 * wb) >> 2) + lane;  // 3*wb divisible by 4 (wb%32==0)
            float4 pv = ((const float4*)points)[i4];
            float4 bv = ((const float4*)closest_bcs)[i4];
            ((float4*)s_inp[wrp])[lane] = pv;
            ((float4*)s_inb[wrp])[lane] = bv;
        }

        // warp-cooperative gather: 1 global wavefront per point
        float4* sw = s_face + wrp * 96;
        int c    = lane & 3;
        int pgrp = lane >> 2;
        #pragma unroll
        for (int r = 0; r < 4; r++) {
            int p_local = 8*r + pgrp;
            int fp = __shfl_sync(0xffffffffu, f, p_local);
            if (c < 3) {
                float4 v = __ldg(&g_face_pack[4*(size_t)fp + c]);
                sw[p_local * 3 + c] = v;
            }
        }
        __syncwarp();

        // strided reads from smem (stride 3 words, coprime 32 -> conflict-free)
        float4 v0 = sw[lane*3 + 0];
        float4 v1 = sw[lane*3 + 1];
        float4 v2 = sw[lane*3 + 2];
        float p0 = s_inp[wrp][3*lane + 0];
        float p1 = s_inp[wrp][3*lane + 1];
        float p2 = s_inp[wrp][3*lane + 2];
        float b0 = fminf(fmaxf(s_inb[wrp][3*lane + 0], 0.0f), 1.0f);
        float b1 = fminf(fmaxf(s_inb[wrp][3*lane + 1], 0.0f), 1.0f);
        float b2 = fminf(fmaxf(s_inb[wrp][3*lane + 2], 0.0f), 1.0f);

        // v0=(t00,t01,t02,t10) v1=(t11,t12,t20,t21) v2=(t22,n0,n1,n2)
        float cpx = fmaf(v0.x, b0, fmaf(v0.w, b1, v1.z * b2));
        float cpy = fmaf(v0.y, b0, fmaf(v1.x, b1, v1.w * b2));
        float cpz = fmaf(v0.z, b0, fmaf(v1.y, b1, v2.x * b2));

        float r0 = cpx - p0;
        float r1 = cpy - p1;
        float r2 = cpz - p2;

        float sq   = fmaf(r0, r0, fmaf(r1, r1, r2 * r2));
        float dist = sqrtf(sq);
        float inv  = (dist == 0.0f) ? 1.0f : (1.0f / dist);

        float rn0 = r0 * inv, rn1 = r1 * inv, rn2 = r2 * inv;

        float dot  = fmaf(r0, v2.y, fmaf(r1, v2.z, r2 * v2.w));
        float sign = (dot > 0.0f) ? -1.0f : 1.0f;

        // narrow sections: already dense
        out[q]    = sign * dist;
        cf_out[q] = (float)f;

        // wide sections: stage strided (conflict-free), store dense
        s_out[wrp][0][3*lane + 0] = rn0;
        s_out[wrp][0][3*lane + 1] = rn1;
        s_out[wrp][0][3*lane + 2] = rn2;
        s_out[wrp][1][3*lane + 0] = cpx;
        s_out[wrp][1][3*lane + 1] = cpy;
        s_out[wrp][1][3*lane + 2] = cpz;
        s_out[wrp][2][3*lane + 0] = b0;
        s_out[wrp][2][3*lane + 1] = b1;
        s_out[wrp][2][3*lane + 2] = b2;
        __syncwarp();

        if (lane < 24) {
            size_t sb = (size_t)3 * wb;     // 3*wb % 4 == 0 -> 16B aligned
            float4 a = ((float4*)s_out[wrp][0])[lane];
            ((float4*)(rn_out + sb))[lane] = a;
            float4 b = ((float4*)s_out[wrp][1])[lane];
            ((float4*)(cp_out + sb))[lane] = b;
            float4 d = ((float4*)s_out[wrp][2])[lane];
            ((float4*)(bc_out + sb))[lane] = d;
        }
    } else if (q < Q) {
        // scalar fallback (partial warps; unused when Q % 32 == 0)
        int f = closest_faces[q];
        float b0 = fminf(fmaxf(closest_bcs[3*q+0], 0.0f), 1.0f);
        float b1 = fminf(fmaxf(closest_bcs[3*q+1], 0.0f), 1.0f);
        float b2 = fminf(fmaxf(closest_bcs[3*q+2], 0.0f), 1.0f);
        float p0 = points[3*q+0], p1 = points[3*q+1], p2 = points[3*q+2];
        float4 v0 = __ldg(&g_face_pack[4*(size_t)f + 0]);
        float4 v1 = __ldg(&g_face_pack[4*(size_t)f + 1]);
        float4 v2 = __ldg(&g_face_pack[4*(size_t)f + 2]);
        float cpx = fmaf(v0.x, b0, fmaf(v0.w, b1, v1.z * b2));
        float cpy = fmaf(v0.y, b0, fmaf(v1.x, b1, v1.w * b2));
        float cpz = fmaf(v0.z, b0, fmaf(v1.y, b1, v2.x * b2));
        float r0 = cpx - p0, r1 = cpy - p1, r2 = cpz - p2;
        float sq = fmaf(r0, r0, fmaf(r1, r1, r2 * r2));
        float dist = sqrtf(sq);
        float inv = (dist == 0.0f) ? 1.0f : (1.0f / dist);
        float dot = fmaf(r0, v2.y, fmaf(r1, v2.z, r2 * v2.w));
        float sign = (dot > 0.0f) ? -1.0f : 1.0f;
        out[q] = sign * dist;
        cf_out[q] = (float)f;
        rn_out[3*q+0] = r0*inv; rn_out[3*q+1] = r1*inv; rn_out[3*q+2] = r2*inv;
        cp_out[3*q+0] = cpx; cp_out[3*q+1] = cpy; cp_out[3*q+2] = cpz;
        bc_out[3*q+0] = b0;  bc_out[3*q+1] = b1;  bc_out[3*q+2] = b2;
    }
}

extern "C" void kernel_launch(void* const* d_in, const int* in_sizes, int n_in,
                              void* d_out, int out_size) {
    const float* triangles     = (const float*)d_in[0];
    const float* face_normals  = (const float*)d_in[1];
    const float* points        = (const float*)d_in[2];
    const int*   closest_faces = (const int*)d_in[3];
    const float* closest_bcs   = (const float*)d_in[4];
    float* out = (float*)d_out;

    int F = in_sizes[0] / 9;
    int Q = in_sizes[3];

    int Fc = F > FMAX ? FMAX : F;
    repack_kernel<<<(Fc * 3 + 255) / 256, 256>>>(triangles, face_normals, Fc);

    int blocks = (Q + 255) / 256;
    sd_smem_kernel<<<blocks, 256>>>(points, closest_faces, closest_bcs, out, Q);
}

// round 11
// speedup vs baseline: 1.7208x; 1.7208x over previous
#include <cuda_runtime.h>
#include <cuda_bf16.h>
#include <cstdint>

#define FMAX 20908

// Repacked per-face record: 4 x float4 = 64B, 128B-aligned so each record
// lies in one 128B line.
// chunk0=(t00,t01,t02,t10) chunk1=(t11,t12,t20,t21) chunk2=(t22,n0,n1,n2) chunk3=pad
__device__ __align__(128) float4 g_face_pack[FMAX * 4];

__global__ __launch_bounds__(256) void repack_kernel(
    const float* __restrict__ triangles,    // [F,3,3]
    const float* __restrict__ face_normals, // [F,3]
    int F)
{
    int i = blockIdx.x * blockDim.x + threadIdx.x;
    if (i >= F * 3) return;
    int f = i / 3;
    int c = i - 3 * f;
    const float* t = triangles + (size_t)f * 9;
    float4 v;
    if (c == 0)      v = make_float4(t[0], t[1], t[2], t[3]);
    else if (c == 1) v = make_float4(t[4], t[5], t[6], t[7]);
    else {
        const float* n = face_normals + (size_t)f * 3;
        v = make_float4(t[8], n[0], n[1], n[2]);
    }
    g_face_pack[4*f + c] = v;
}

__device__ __forceinline__ void cp_async16(uint32_t smem_addr, const void* gptr) {
    asm volatile("cp.async.ca.shared.global [%0], [%1], 16;"
                 :: "r"(smem_addr), "l"(gptr) : "memory");
}

// R5 structure (1 point/thread, 256 threads = 8 warps) with the gather done
// via cp.async (no register landing, no LDG->STS serialization) and the face
// index broadcast done via L1-hot LDG instead of SHFL.
__global__ __launch_bounds__(256) void sd_async_kernel(
    const float* __restrict__ points,        // [Q,3]
    const int*   __restrict__ closest_faces, // [Q]
    const float* __restrict__ closest_bcs,   // [Q,3]
    float* __restrict__ out,
    int Q)
{
    // 8 warps x 32 points x 3 float4, 48B record stride (conflict-free LDS.128)
    __shared__ float4 s_face[8 * 32 * 3];    // 12 KB

    int tid  = threadIdx.x;
    int lane = tid & 31;
    int wrp  = tid >> 5;
    int q    = blockIdx.x * blockDim.x + tid;
    int wb   = q - lane;
    if (wb >= Q) return;
    bool full = (wb + 32 <= Q);

    float* rn_out = out + (size_t)Q;
    float* cp_out = out + (size_t)4 * Q;
    float* cf_out = out + (size_t)7 * Q;
    float* bc_out = out + (size_t)8 * Q;

    if (full) {
        // ---- fire-and-forget cooperative gather via cp.async ----
        // lane 4p+c copies chunk c (c<3) of the round's point p into staging.
        uint32_t sw_base = (uint32_t)__cvta_generic_to_shared(s_face + wrp * 96);
        int c    = lane & 3;
        int pgrp = lane >> 2;
        #pragma unroll
        for (int r = 0; r < 4; r++) {
            int p_local = 8*r + pgrp;
            int fp = closest_faces[wb + p_local];   // L1-hot broadcast line
            if (c < 3) {
                cp_async16(sw_base + (uint32_t)(p_local * 48 + c * 16),
                           &g_face_pack[4*(size_t)fp + c]);
            }
        }
        asm volatile("cp.async.commit_group;" ::: "memory");

        // ---- streaming loads overlap the async copies ----
        int f = closest_faces[q];
        float c0 = closest_bcs[3*q + 0];
        float c1 = closest_bcs[3*q + 1];
        float c2 = closest_bcs[3*q + 2];
        float p0 = points[3*q + 0];
        float p1 = points[3*q + 1];
        float p2 = points[3*q + 2];

        asm volatile("cp.async.wait_group 0;" ::: "memory");
        __syncwarp();

        const float4* sw = s_face + wrp * 96;
        float4 v0 = sw[lane*3 + 0];
        float4 v1 = sw[lane*3 + 1];
        float4 v2 = sw[lane*3 + 2];

        float b0 = fminf(fmaxf(c0, 0.0f), 1.0f);
        float b1 = fminf(fmaxf(c1, 0.0f), 1.0f);
        float b2 = fminf(fmaxf(c2, 0.0f), 1.0f);

        // v0=(t00,t01,t02,t10) v1=(t11,t12,t20,t21) v2=(t22,n0,n1,n2)
        float cpx = fmaf(v0.x, b0, fmaf(v0.w, b1, v1.z * b2));
        float cpy = fmaf(v0.y, b0, fmaf(v1.x, b1, v1.w * b2));
        float cpz = fmaf(v0.z, b0, fmaf(v1.y, b1, v2.x * b2));

        float r0 = cpx - p0;
        float r1 = cpy - p1;
        float r2 = cpz - p2;

        float sq   = fmaf(r0, r0, fmaf(r1, r1, r2 * r2));
        float dist = sqrtf(sq);
        float inv  = (dist == 0.0f) ? 1.0f : (1.0f / dist);

        float rn0 = r0 * inv, rn1 = r1 * inv, rn2 = r2 * inv;

        float dot  = fmaf(r0, v2.y, fmaf(r1, v2.z, r2 * v2.w));
        float sign = (dot > 0.0f) ? -1.0f : 1.0f;

        out[q]    = sign * dist;
        cf_out[q] = (float)f;
        rn_out[3*q+0] = rn0; rn_out[3*q+1] = rn1; rn_out[3*q+2] = rn2;
        cp_out[3*q+0] = cpx; cp_out[3*q+1] = cpy; cp_out[3*q+2] = cpz;
        bc_out[3*q+0] = b0;  bc_out[3*q+1] = b1;  bc_out[3*q+2] = b2;
    } else if (q < Q) {
        // scalar fallback (partial warp; unused when Q % 32 == 0)
        int f = closest_faces[q];
        float b0 = fminf(fmaxf(closest_bcs[3*q+0], 0.0f), 1.0f);
        float b1 = fminf(fmaxf(closest_bcs[3*q+1], 0.0f), 1.0f);
        float b2 = fminf(fmaxf(closest_bcs[3*q+2], 0.0f), 1.0f);
        float p0 = points[3*q+0], p1 = points[3*q+1], p2 = points[3*q+2];
        float4 v0 = __ldg(&g_face_pack[4*(size_t)f + 0]);
        float4 v1 = __ldg(&g_face_pack[4*(size_t)f + 1]);
        float4 v2 = __ldg(&g_face_pack[4*(size_t)f + 2]);
        float cpx = fmaf(v0.x, b0, fmaf(v0.w, b1, v1.z * b2));
        float cpy = fmaf(v0.y, b0, fmaf(v1.x, b1, v1.w * b2));
        float cpz = fmaf(v0.z, b0, fmaf(v1.y, b1, v2.x * b2));
        float r0 = cpx - p0, r1 = cpy - p1, r2 = cpz - p2;
        float sq = fmaf(r0, r0, fmaf(r1, r1, r2 * r2));
        float dist = sqrtf(sq);
        float inv = (dist == 0.0f) ? 1.0f : (1.0f / dist);
        float dot = fmaf(r0, v2.y, fmaf(r1, v2.z, r2 * v2.w));
        float sign = (dot > 0.0f) ? -1.0f : 1.0f;
        out[q] = sign * dist;
        cf_out[q] = (float)f;
        rn_out[3*q+0] = r0*inv; rn_out[3*q+1] = r1*inv; rn_out[3*q+2] = r2*inv;
        cp_out[3*q+0] = cpx; cp_out[3*q+1] = cpy; cp_out[3*q+2] = cpz;
        bc_out[3*q+0] = b0;  bc_out[3*q+1] = b1;  bc_out[3*q+2] = b2;
    }
}

extern "C" void kernel_launch(void* const* d_in, const int* in_sizes, int n_in,
                              void* d_out, int out_size) {
    const float* triangles     = (const float*)d_in[0];
    const float* face_normals  = (const float*)d_in[1];
    const float* points        = (const float*)d_in[2];
    const int*   closest_faces = (const int*)d_in[3];
    const float* closest_bcs   = (const float*)d_in[4];
    float* out = (float*)d_out;

    int F = in_sizes[0] / 9;
    int Q = in_sizes[3];

    int Fc = F > FMAX ? FMAX : F;
    repack_kernel<<<(Fc * 3 + 255) / 256, 256>>>(triangles, face_normals, Fc);

    int blocks = (Q + 255) / 256;
    sd_async_kernel<<<blocks, 256>>>(points, closest_faces, closest_bcs, out, Q);
}